// round 2
// baseline (speedup 1.0000x reference)
#include <cuda_runtime.h>

#define B_   64
#define T_   13
#define N_   325
#define H_   64
#define C_   4
#define S_   4
#define P_   12
#define NB_  1300
#define OFF_ 975
#define NH_  (N_*H_)        // 20800
#define BNH_ (B_*NH_)       // 1331200

// ---------------- scratch (device globals; no runtime alloc allowed) --------
__device__ float  g_gf  [BNH_];
__device__ float  g_res [BNH_];
__device__ float  g_h3  [BNH_];
__device__ float  g_cr  [BNH_];
__device__ float  g_last[BNH_];
__device__ float  g_H0  [2][C_][BNH_];   // layer-0 outputs per (mat, channel)
__device__ float  g_C1  [2][C_][BNH_];   // layer-1 outputs (ca / cp)
__device__ float  g_Wsum[2][C_][2][H_*H_];
__device__ int    g_cols[2][N_][N_];
__device__ float  g_vals[2][N_][N_];
__device__ int    g_cnt [2][N_];
__device__ double g_sums[2];

// ---------------- prep: Wsum[mat][c][l] = W[c,l,0] + W[c,l,1] ---------------
__global__ void k_wsum(const float* __restrict__ aw, const float* __restrict__ pw) {
    int idx = blockIdx.x * blockDim.x + threadIdx.x;   // 65536 total
    if (idx >= 2 * C_ * 2 * H_ * H_) return;
    int mat = idx >> 15;
    int r   = idx & 32767;
    int c   = r >> 13;
    int l   = (r >> 12) & 1;
    int e   = r & 4095;
    const float* src = mat ? pw : aw;
    int base = ((c * 2 + l) * 2) * 4096;               // [c][l][j][k][h]
    ((float*)g_Wsum)[idx] = src[base + e] + src[base + 4096 + e];
}

// ---------------- prep: compact nonzeros of the last diagonal block ---------
__global__ void k_compact(const float* __restrict__ adjf, const float* __restrict__ peaf) {
    int rowid = blockIdx.x;            // 0..2*N_-1
    int mat = rowid / N_;
    int n   = rowid % N_;
    const float* A = mat ? peaf : adjf;
    int lane = threadIdx.x;
    int cnt = 0;
    for (int base = 0; base < N_; base += 32) {
        int m = base + lane;
        float w = (m < N_) ? A[(long)(OFF_ + n) * NB_ + OFF_ + m] : 0.f;
        unsigned mask = __ballot_sync(0xffffffffu, w != 0.f);
        if (w != 0.f) {
            int pos = cnt + __popc(mask & ((1u << lane) - 1u));
            g_cols[mat][n][pos] = m;
            g_vals[mat][n][pos] = w;
        }
        cnt += __popc(mask);
    }
    if (lane == 0) g_cnt[mat][n] = cnt;
}

// ---------------- per-checkpoint: gf / residual / h3 (x computed inline) ----
__global__ void k_A(const float* __restrict__ inp, const float* __restrict__ w_in,
                    const float* __restrict__ b_in, const float* __restrict__ res_w,
                    const float* __restrict__ res_b, const float* __restrict__ gcw,
                    const float* __restrict__ gcb, int ck, int left) {
    int idx = blockIdx.x * blockDim.x + threadIdx.x;
    if (idx >= BNH_) return;
    if (idx == 0) { g_sums[0] = 0.0; g_sums[1] = 0.0; }
    int h = idx & 63;
    int n = (idx >> 6) % N_;
    int b = idx / NH_;
    float w0 = w_in[h], w1 = w_in[64 + h], bi = b_in[h];
    float gf = 0.f, rs = 0.f, v = 0.f;
#pragma unroll
    for (int s = 0; s < 4; ++s) {
        if (ck > 0 && s == 0) {
            v = g_last[idx];
        } else {
            int t = (ck == 0) ? s : (left + s - 1);
            const float* ip = inp + (((long)b * T_ + t) * N_ + n) * 2;
            v = ip[0] * w0 + ip[1] * w1 + bi;
        }
        gf += gcw[s] * v;
        rs += res_w[s] * v;
    }
    g_gf[idx]  = gf + gcb[0];
    g_res[idx] = rs + res_b[0];
    g_h3[idx]  = v;   // slice s=3
}

// ---------------- GCN layer 0: m0 = adj @ h3 (shared), then 4 channel GEMMs -
__global__ void k_layer0(int mat, const float* __restrict__ gb) {
    __shared__ float sm[16][64];
    int n  = blockIdx.x;
    int bg = blockIdx.y;               // 16-batch group
    int t  = threadIdx.x;
    int hd = t & 63;
    int lq = t >> 6;                   // 0..3
    int cnt = g_cnt[mat][n];
    const int*   cols = g_cols[mat][n];
    const float* vals = g_vals[mat][n];
    int b0 = bg * 16 + lq * 4;
    float acc[4] = {0.f, 0.f, 0.f, 0.f};
    for (int i = 0; i < cnt; ++i) {
        int m = cols[i];
        float w = vals[i];
        const float* hp = g_h3 + m * 64 + hd;
#pragma unroll
        for (int j = 0; j < 4; ++j) acc[j] += w * hp[(b0 + j) * NH_];
    }
#pragma unroll
    for (int j = 0; j < 4; ++j) sm[lq * 4 + j][hd] = acc[j];
    __syncthreads();
#pragma unroll
    for (int c = 0; c < C_; ++c) {
        const float* W = g_Wsum[mat][c][0];
        float bias = gb[(c * 2 + 0) * 64 + hd];
        float out[4] = {bias, bias, bias, bias};
        for (int kk = 0; kk < 64; ++kk) {
            float wv = __ldg(&W[kk * 64 + hd]);
#pragma unroll
            for (int j = 0; j < 4; ++j) out[j] += sm[lq * 4 + j][kk] * wv;
        }
#pragma unroll
        for (int j = 0; j < 4; ++j) {
            float o = out[j] > 0.f ? out[j] : 0.f;
            g_H0[mat][c][(b0 + j) * NH_ + n * 64 + hd] = o;
        }
    }
}

// ---------------- GCN layer 1: per-channel SpMM + GEMM ----------------------
__global__ void k_layer1(int mat, const float* __restrict__ gb) {
    __shared__ float sm[16][64];
    int n  = blockIdx.x;
    int bg = blockIdx.y;
    int c  = blockIdx.z;
    int t  = threadIdx.x;
    int hd = t & 63;
    int lq = t >> 6;
    int cnt = g_cnt[mat][n];
    const int*   cols = g_cols[mat][n];
    const float* vals = g_vals[mat][n];
    const float* hsrc = g_H0[mat][c];
    int b0 = bg * 16 + lq * 4;
    float acc[4] = {0.f, 0.f, 0.f, 0.f};
    for (int i = 0; i < cnt; ++i) {
        int m = cols[i];
        float w = vals[i];
        const float* hp = hsrc + m * 64 + hd;
#pragma unroll
        for (int j = 0; j < 4; ++j) acc[j] += w * hp[(b0 + j) * NH_];
    }
#pragma unroll
    for (int j = 0; j < 4; ++j) sm[lq * 4 + j][hd] = acc[j];
    __syncthreads();
    const float* W = g_Wsum[mat][c][1];
    float bias = gb[(c * 2 + 1) * 64 + hd];
    float out[4] = {bias, bias, bias, bias};
    for (int kk = 0; kk < 64; ++kk) {
        float wv = __ldg(&W[kk * 64 + hd]);
#pragma unroll
        for (int j = 0; j < 4; ++j) out[j] += sm[lq * 4 + j][kk] * wv;
    }
#pragma unroll
    for (int j = 0; j < 4; ++j) {
        float o = out[j] > 0.f ? out[j] : 0.f;
        g_C1[mat][c][(b0 + j) * NH_ + n * 64 + hd] = o;
    }
}

// ---------------- gate -> combine -> reduce -> +residual --------------------
__global__ void k_gate(const float* __restrict__ g1w, const float* __restrict__ g1b,
                       const float* __restrict__ g2w, const float* __restrict__ g2b,
                       const float* __restrict__ rw,  const float* __restrict__ rb) {
    __shared__ float sh_in[4][64];
    __shared__ float sh_g1[4][64];
    __shared__ float sh_gr[4][256];
    int t  = threadIdx.x;
    int h  = t & 63;
    int rl = t >> 6;
    int row = blockIdx.x * 4 + rl;     // (b,n) flattened, 20800 rows
    int base = row * 64;
    sh_in[rl][h] = g_gf[base + h];
    __syncthreads();
    float a = g1b[h];
    for (int k = 0; k < 64; ++k) a += sh_in[rl][k] * __ldg(&g1w[k * 64 + h]);
    sh_g1[rl][h] = a > 0.f ? a : 0.f;
    __syncthreads();
#pragma unroll
    for (int q = 0; q < 4; ++q) {
        int h2 = q * 64 + h;
        float s = g2b[h2];
        for (int k = 0; k < 64; ++k) s += sh_g1[rl][k] * __ldg(&g2w[k * 256 + h2]);
        float gate = 1.f / (1.f + expf(-s));
        float ca  = g_C1[0][q][base + h];
        float cpv = g_C1[1][q][base + h];
        sh_gr[rl][h2] = gate * ca + (1.f - gate) * cpv;
    }
    __syncthreads();
    float o = rb[h];
    for (int k = 0; k < 256; ++k) o += sh_gr[rl][k] * __ldg(&rw[k * 64 + h]);
    g_cr[base + h] = o + g_res[base + h];
}

// ---------------- global mean/var reduction ---------------------------------
__global__ void k_sum() {
    __shared__ double ss[256], sq[256];
    double s = 0.0, q = 0.0;
    for (int i = blockIdx.x * blockDim.x + threadIdx.x; i < BNH_;
         i += gridDim.x * blockDim.x) {
        double v = (double)g_cr[i];
        s += v; q += v * v;
    }
    ss[threadIdx.x] = s; sq[threadIdx.x] = q;
    __syncthreads();
    for (int o = 128; o > 0; o >>= 1) {
        if (threadIdx.x < o) {
            ss[threadIdx.x] += ss[threadIdx.x + o];
            sq[threadIdx.x] += sq[threadIdx.x + o];
        }
        __syncthreads();
    }
    if (threadIdx.x == 0) {
        atomicAdd(&g_sums[0], ss[0]);
        atomicAdd(&g_sums[1], sq[0]);
    }
}

// ---------------- whole-tensor layernorm ------------------------------------
__global__ void k_norm() {
    __shared__ float s_mu, s_r;
    if (threadIdx.x == 0) {
        double mu  = g_sums[0] / (double)BNH_;
        double var = g_sums[1] / (double)BNH_ - mu * mu;
        s_mu = (float)mu;
        s_r  = (float)rsqrt(var + 1e-5);
    }
    __syncthreads();
    int i = blockIdx.x * blockDim.x + threadIdx.x;
    if (i < BNH_) g_last[i] = (g_cr[i] - s_mu) * s_r;
}

// ---------------- final: 1x1 conv over P + linear H->1 ----------------------
__global__ void k_out(const float* __restrict__ cw, const float* __restrict__ cb,
                      const float* __restrict__ lw, const float* __restrict__ lb,
                      float* __restrict__ out) {
    __shared__ float red[4][2];
    int t = threadIdx.x;
    int h = t & 63;
    int rl = t >> 6;
    int row = blockIdx.x * 4 + rl;     // (b,n)
    int b = row / N_, n = row % N_;
    float v   = g_last[row * 64 + h];
    float lin = lw[h];
    int lane = t & 31;
    int w2   = (t >> 5) & 1;
    for (int p = 0; p < P_; ++p) {
        float x = cw[p] * v + cb[p];
        x = x > 0.f ? x : 0.f;
        float s = x * lin;
#pragma unroll
        for (int o = 16; o > 0; o >>= 1) s += __shfl_down_sync(0xffffffffu, s, o);
        if (lane == 0) red[rl][w2] = s;
        __syncthreads();
        if (h == 0) out[((long)b * P_ + p) * N_ + n] = red[rl][0] + red[rl][1] + lb[0];
        __syncthreads();
    }
}

// ---------------- launcher ---------------------------------------------------
extern "C" void kernel_launch(void* const* d_in, const int* in_sizes, int n_in,
                              void* d_out, int out_size) {
    const float* inputs    = (const float*)d_in[0];
    const float* adj_fwd   = (const float*)d_in[1];
    const float* pea_fwd   = (const float*)d_in[3];
    const float* w_in      = (const float*)d_in[5];
    const float* b_in      = (const float*)d_in[6];
    const float* res_w     = (const float*)d_in[7];
    const float* res_b     = (const float*)d_in[8];
    const float* gconv_w   = (const float*)d_in[9];
    const float* gconv_b   = (const float*)d_in[10];
    const float* gate1_w   = (const float*)d_in[11];
    const float* gate1_b   = (const float*)d_in[12];
    const float* gate2_w   = (const float*)d_in[13];
    const float* gate2_b   = (const float*)d_in[14];
    const float* reduce_w  = (const float*)d_in[15];
    const float* reduce_b  = (const float*)d_in[16];
    const float* gcn_adj_w = (const float*)d_in[17];
    const float* gcn_adj_b = (const float*)d_in[18];
    const float* gcn_pea_w = (const float*)d_in[19];
    const float* gcn_pea_b = (const float*)d_in[20];
    const float* out_cw    = (const float*)d_in[21];
    const float* out_cb    = (const float*)d_in[22];
    const float* out_lw    = (const float*)d_in[23];
    const float* out_lb    = (const float*)d_in[24];
    float* out = (float*)d_out;

    k_wsum<<<256, 256>>>(gcn_adj_w, gcn_pea_w);
    k_compact<<<2 * N_, 32>>>(adj_fwd, pea_fwd);

    const int lefts[4] = {0, 4, 7, 10};
    for (int ck = 0; ck < 4; ++ck) {
        k_A<<<BNH_ / 256, 256>>>(inputs, w_in, b_in, res_w, res_b,
                                 gconv_w, gconv_b, ck, lefts[ck]);
        dim3 gl0(N_, 4);
        k_layer0<<<gl0, 256>>>(0, gcn_adj_b);
        k_layer0<<<gl0, 256>>>(1, gcn_pea_b);
        dim3 gl1(N_, 4, C_);
        k_layer1<<<gl1, 256>>>(0, gcn_adj_b);
        k_layer1<<<gl1, 256>>>(1, gcn_pea_b);
        k_gate<<<BNH_ / 64 / 4, 256>>>(gate1_w, gate1_b, gate2_w, gate2_b,
                                       reduce_w, reduce_b);
        k_sum<<<512, 256>>>();
        k_norm<<<BNH_ / 256, 256>>>();
    }
    k_out<<<(B_ * N_) / 4, 256>>>(out_cw, out_cb, out_lw, out_lb, out);
}